// round 1
// baseline (speedup 1.0000x reference)
#include <cuda_runtime.h>
#include <math.h>

#define B_ 2
#define S_ 2048
#define C_ 1024
#define H_ 16
#define D_ 64
#define BH_ (B_*H_)

// ---------------- scratch (static device globals; no allocation) ----------------
__device__ float g_rr[S_*D_];                         // rel-pos rows, index = relative distance p
__device__ float g_Q[(size_t)BH_*S_*D_];
__device__ float g_K[(size_t)BH_*S_*D_];
__device__ float g_V[(size_t)BH_*S_*D_];
__device__ float g_T3[BH_*S_];                        // u . K
__device__ float g_D[(size_t)BH_*S_*S_];              // (Q+v) @ rr^T
__device__ float g_SC[(size_t)BH_*S_*S_];             // scores -> attn (in place)
__device__ float g_CTX[(size_t)B_*S_*C_];             // attention output, [b,s,h*d]

// ---------------- sinusoid relative-position table ----------------
// rr[p][j]     = sin(p * invf[j])   j<32
// rr[p][32+j]  = cos(p * invf[j])
__global__ void rr_kernel(float* __restrict__ rr) {
    int p = blockIdx.x;
    int i = threadIdx.x;                              // 0..63
    double invf = exp(-((double)(i & 31)) * (log(10000.0) / 32.0));
    double ang = (double)p * invf;
    rr[p * D_ + i] = (i < 32) ? (float)sin(ang) : (float)cos(ang);
}

// ---------------- generic 128x128x8 SGEMM (NN), optional bias / head-layout out ----------------
__global__ void sgemm_nn(const float* __restrict__ A, const float* __restrict__ Bm,
                         const float* __restrict__ bias, float* __restrict__ Co,
                         int M, int N, int K, int headed)
{
    __shared__ float As[8][128];
    __shared__ float Bs[8][128];
    const int tid = threadIdx.x;
    const int m0 = blockIdx.y * 128;
    const int n0 = blockIdx.x * 128;
    const int tx = tid & 15, ty = tid >> 4;
    const int arow = tid >> 1, acol = (tid & 1) * 4;
    const int brow = tid >> 5, bcol = (tid & 31) * 4;
    float acc[8][8];
    #pragma unroll
    for (int i = 0; i < 8; i++)
        #pragma unroll
        for (int j = 0; j < 8; j++) acc[i][j] = 0.f;

    for (int kt = 0; kt < K; kt += 8) {
        float4 av = *(const float4*)(A + (size_t)(m0 + arow) * K + kt + acol);
        As[acol + 0][arow] = av.x;
        As[acol + 1][arow] = av.y;
        As[acol + 2][arow] = av.z;
        As[acol + 3][arow] = av.w;
        *(float4*)&Bs[brow][bcol] =
            *(const float4*)(Bm + (size_t)(kt + brow) * N + n0 + bcol);
        __syncthreads();
        #pragma unroll
        for (int k = 0; k < 8; k++) {
            float a[8], b[8];
            #pragma unroll
            for (int i = 0; i < 8; i++) a[i] = As[k][ty * 8 + i];
            #pragma unroll
            for (int j = 0; j < 8; j++) b[j] = Bs[k][tx * 8 + j];
            #pragma unroll
            for (int i = 0; i < 8; i++)
                #pragma unroll
                for (int j = 0; j < 8; j++) acc[i][j] += a[i] * b[j];
        }
        __syncthreads();
    }
    #pragma unroll
    for (int i = 0; i < 8; i++) {
        int m = m0 + ty * 8 + i;
        #pragma unroll
        for (int j = 0; j < 8; j++) {
            int n = n0 + tx * 8 + j;
            float v = acc[i][j];
            if (bias) v += bias[n];
            if (headed) {
                int b = m >> 11, s = m & (S_ - 1), h = n >> 6, d = n & 63;
                Co[(((size_t)(b * H_ + h)) * S_ + s) * D_ + d] = v;
            } else {
                Co[(size_t)m * N + n] = v;
            }
        }
    }
}

// ---------------- T3[bh][k] = u[h] . K[bh][k] ----------------
__global__ void t3_kernel(const float* __restrict__ Km, const float* __restrict__ u,
                          float* __restrict__ T3)
{
    int warp = (blockIdx.x * blockDim.x + threadIdx.x) >> 5;   // one row per warp
    int lane = threadIdx.x & 31;
    if (warp >= BH_ * S_) return;
    int bh = warp >> 11;                                       // / S_
    int h = bh & (H_ - 1);
    const float* kr = Km + (size_t)warp * D_;
    float s = kr[lane] * u[h * D_ + lane] + kr[lane + 32] * u[h * D_ + lane + 32];
    #pragma unroll
    for (int o = 16; o; o >>= 1) s += __shfl_xor_sync(0xffffffffu, s, o);
    if (lane == 0) T3[warp] = s;
}

// ---------------- D[bh][q][p] = (Q[bh][q] + v[h]) . rr[p]   (batched A@B^T, K=64) ----------------
__global__ void relD_kernel(const float* __restrict__ Q, const float* __restrict__ rr,
                            const float* __restrict__ vb, float* __restrict__ D)
{
    const int bh = blockIdx.z, h = bh & (H_ - 1);
    const float* Aq = Q + (size_t)bh * S_ * D_;
    __shared__ float As[8][128];
    __shared__ float Bs[8][128];
    const int tid = threadIdx.x;
    const int q0 = blockIdx.y * 128, p0 = blockIdx.x * 128;
    const int tx = tid & 15, ty = tid >> 4;
    const int row = tid >> 1, kc = (tid & 1) * 4;
    float acc[8][8];
    #pragma unroll
    for (int i = 0; i < 8; i++)
        #pragma unroll
        for (int j = 0; j < 8; j++) acc[i][j] = 0.f;

    for (int kt = 0; kt < D_; kt += 8) {
        float4 av = *(const float4*)(Aq + (size_t)(q0 + row) * D_ + kt + kc);
        float4 vv = *(const float4*)(vb + h * D_ + kt + kc);
        As[kc + 0][row] = av.x + vv.x;
        As[kc + 1][row] = av.y + vv.y;
        As[kc + 2][row] = av.z + vv.z;
        As[kc + 3][row] = av.w + vv.w;
        float4 bv = *(const float4*)(rr + (size_t)(p0 + row) * D_ + kt + kc);
        Bs[kc + 0][row] = bv.x;
        Bs[kc + 1][row] = bv.y;
        Bs[kc + 2][row] = bv.z;
        Bs[kc + 3][row] = bv.w;
        __syncthreads();
        #pragma unroll
        for (int k = 0; k < 8; k++) {
            float a[8], b[8];
            #pragma unroll
            for (int i = 0; i < 8; i++) a[i] = As[k][ty * 8 + i];
            #pragma unroll
            for (int j = 0; j < 8; j++) b[j] = Bs[k][tx * 8 + j];
            #pragma unroll
            for (int i = 0; i < 8; i++)
                #pragma unroll
                for (int j = 0; j < 8; j++) acc[i][j] += a[i] * b[j];
        }
        __syncthreads();
    }
    float* Dp = D + (size_t)bh * S_ * S_;
    #pragma unroll
    for (int i = 0; i < 8; i++)
        #pragma unroll
        for (int j = 0; j < 8; j++)
            Dp[(size_t)(q0 + ty * 8 + i) * S_ + p0 + tx * 8 + j] = acc[i][j];
}

// ---------------- scores: QK^T + T3 + rel_shift(D), scaled (batched, K=64) ----------------
__global__ void scores_kernel(const float* __restrict__ Q, const float* __restrict__ Km,
                              const float* __restrict__ T3, const float* __restrict__ D,
                              float* __restrict__ SC)
{
    const int bh = blockIdx.z;
    const float* Aq = Q + (size_t)bh * S_ * D_;
    const float* Bk = Km + (size_t)bh * S_ * D_;
    __shared__ float As[8][128];
    __shared__ float Bs[8][128];
    const int tid = threadIdx.x;
    const int q0 = blockIdx.y * 128, n0 = blockIdx.x * 128;
    const int tx = tid & 15, ty = tid >> 4;
    const int row = tid >> 1, kc = (tid & 1) * 4;
    float acc[8][8];
    #pragma unroll
    for (int i = 0; i < 8; i++)
        #pragma unroll
        for (int j = 0; j < 8; j++) acc[i][j] = 0.f;

    for (int kt = 0; kt < D_; kt += 8) {
        float4 av = *(const float4*)(Aq + (size_t)(q0 + row) * D_ + kt + kc);
        As[kc + 0][row] = av.x;
        As[kc + 1][row] = av.y;
        As[kc + 2][row] = av.z;
        As[kc + 3][row] = av.w;
        float4 bv = *(const float4*)(Bk + (size_t)(n0 + row) * D_ + kt + kc);
        Bs[kc + 0][row] = bv.x;
        Bs[kc + 1][row] = bv.y;
        Bs[kc + 2][row] = bv.z;
        Bs[kc + 3][row] = bv.w;
        __syncthreads();
        #pragma unroll
        for (int k = 0; k < 8; k++) {
            float a[8], b[8];
            #pragma unroll
            for (int i = 0; i < 8; i++) a[i] = As[k][ty * 8 + i];
            #pragma unroll
            for (int j = 0; j < 8; j++) b[j] = Bs[k][tx * 8 + j];
            #pragma unroll
            for (int i = 0; i < 8; i++)
                #pragma unroll
                for (int j = 0; j < 8; j++) acc[i][j] += a[i] * b[j];
        }
        __syncthreads();
    }
    const float* Dp = D + (size_t)bh * S_ * S_;
    const float* t3p = T3 + bh * S_;
    float* scp = SC + (size_t)bh * S_ * S_;
    #pragma unroll
    for (int i = 0; i < 8; i++) {
        int q = q0 + ty * 8 + i;
        #pragma unroll
        for (int j = 0; j < 8; j++) {
            int k = n0 + tx * 8 + j;
            int dq = q - k;
            float sh;
            if (dq >= 0)       sh = Dp[(size_t)q * S_ + dq];
            else if (dq == -1) sh = 0.f;
            else               sh = Dp[(size_t)(q + 1) * S_ + (S_ + 1 + dq)];
            scp[(size_t)q * S_ + k] = (acc[i][j] + t3p[k] + sh) * 0.125f;
        }
    }
}

// ---------------- row softmax over 2048, in place ----------------
__global__ void softmax_kernel(float* __restrict__ SC)
{
    float* p = SC + (size_t)blockIdx.x * S_;
    const int tid = threadIdx.x;                      // 256 threads, 8 elems each
    float4 v0 = ((float4*)p)[tid];
    float4 v1 = ((float4*)p)[tid + 256];
    float m = fmaxf(fmaxf(fmaxf(v0.x, v0.y), fmaxf(v0.z, v0.w)),
                    fmaxf(fmaxf(v1.x, v1.y), fmaxf(v1.z, v1.w)));
    __shared__ float red[8];
    #pragma unroll
    for (int o = 16; o; o >>= 1) m = fmaxf(m, __shfl_xor_sync(0xffffffffu, m, o));
    if ((tid & 31) == 0) red[tid >> 5] = m;
    __syncthreads();
    m = red[0];
    #pragma unroll
    for (int i = 1; i < 8; i++) m = fmaxf(m, red[i]);
    __syncthreads();

    v0.x = expf(v0.x - m); v0.y = expf(v0.y - m);
    v0.z = expf(v0.z - m); v0.w = expf(v0.w - m);
    v1.x = expf(v1.x - m); v1.y = expf(v1.y - m);
    v1.z = expf(v1.z - m); v1.w = expf(v1.w - m);
    float s = v0.x + v0.y + v0.z + v0.w + v1.x + v1.y + v1.z + v1.w;
    #pragma unroll
    for (int o = 16; o; o >>= 1) s += __shfl_xor_sync(0xffffffffu, s, o);
    if ((tid & 31) == 0) red[tid >> 5] = s;
    __syncthreads();
    s = red[0];
    #pragma unroll
    for (int i = 1; i < 8; i++) s += red[i];
    float inv = 1.f / s;
    v0.x *= inv; v0.y *= inv; v0.z *= inv; v0.w *= inv;
    v1.x *= inv; v1.y *= inv; v1.z *= inv; v1.w *= inv;
    ((float4*)p)[tid] = v0;
    ((float4*)p)[tid + 256] = v1;
}

// ---------------- ctx[b][q][h*64+d] = attn[bh] @ V[bh]   (M=2048, N=64, K=2048) ----------------
__global__ void av_kernel(const float* __restrict__ SC, const float* __restrict__ V,
                          float* __restrict__ CTX)
{
    const int bh = blockIdx.z, b = bh >> 4, h = bh & 15;
    const float* A = SC + (size_t)bh * S_ * S_;
    const float* Bv = V + (size_t)bh * S_ * D_;
    __shared__ float As[16][128];
    __shared__ float Bs[16][64];
    const int tid = threadIdx.x;
    const int q0 = blockIdx.y * 128;
    const int tx = tid & 15, ty = tid >> 4;
    const int arow = tid >> 1, acol = (tid & 1) * 8;
    const int brow = tid >> 4, bcol = (tid & 15) * 4;
    float acc[8][4];
    #pragma unroll
    for (int i = 0; i < 8; i++)
        #pragma unroll
        for (int j = 0; j < 4; j++) acc[i][j] = 0.f;

    for (int kt = 0; kt < S_; kt += 16) {
        const float* ap = A + (size_t)(q0 + arow) * S_ + kt + acol;
        float4 a0 = *(const float4*)(ap);
        float4 a1 = *(const float4*)(ap + 4);
        As[acol + 0][arow] = a0.x; As[acol + 1][arow] = a0.y;
        As[acol + 2][arow] = a0.z; As[acol + 3][arow] = a0.w;
        As[acol + 4][arow] = a1.x; As[acol + 5][arow] = a1.y;
        As[acol + 6][arow] = a1.z; As[acol + 7][arow] = a1.w;
        *(float4*)&Bs[brow][bcol] = *(const float4*)(Bv + (size_t)(kt + brow) * D_ + bcol);
        __syncthreads();
        #pragma unroll
        for (int k = 0; k < 16; k++) {
            float a[8], bb[4];
            #pragma unroll
            for (int i = 0; i < 8; i++) a[i] = As[k][ty * 8 + i];
            #pragma unroll
            for (int j = 0; j < 4; j++) bb[j] = Bs[k][tx * 4 + j];
            #pragma unroll
            for (int i = 0; i < 8; i++)
                #pragma unroll
                for (int j = 0; j < 4; j++) acc[i][j] += a[i] * bb[j];
        }
        __syncthreads();
    }
    #pragma unroll
    for (int i = 0; i < 8; i++)
        #pragma unroll
        for (int j = 0; j < 4; j++)
            CTX[((size_t)b * S_ + q0 + ty * 8 + i) * C_ + h * D_ + tx * 4 + j] = acc[i][j];
}

// ---------------- launch ----------------
extern "C" void kernel_launch(void* const* d_in, const int* in_sizes, int n_in,
                              void* d_out, int out_size)
{
    const float* x  = (const float*)d_in[0];
    const float* Wq = (const float*)d_in[1];
    const float* Wk = (const float*)d_in[2];
    const float* Wv = (const float*)d_in[3];
    const float* u  = (const float*)d_in[4];
    const float* v  = (const float*)d_in[5];
    const float* Wo = (const float*)d_in[6];
    const float* bo = (const float*)d_in[7];
    float* out = (float*)d_out;

    float *rr, *Q, *K, *V, *T3, *D, *SC, *CTX;
    cudaGetSymbolAddress((void**)&rr,  g_rr);
    cudaGetSymbolAddress((void**)&Q,   g_Q);
    cudaGetSymbolAddress((void**)&K,   g_K);
    cudaGetSymbolAddress((void**)&V,   g_V);
    cudaGetSymbolAddress((void**)&T3,  g_T3);
    cudaGetSymbolAddress((void**)&D,   g_D);
    cudaGetSymbolAddress((void**)&SC,  g_SC);
    cudaGetSymbolAddress((void**)&CTX, g_CTX);

    rr_kernel<<<S_, 64>>>(rr);

    dim3 gproj(C_ / 128, (B_ * S_) / 128);            // (8, 32)
    sgemm_nn<<<gproj, 256>>>(x, Wq, nullptr, Q, B_ * S_, C_, C_, 1);
    sgemm_nn<<<gproj, 256>>>(x, Wk, nullptr, K, B_ * S_, C_, C_, 1);
    sgemm_nn<<<gproj, 256>>>(x, Wv, nullptr, V, B_ * S_, C_, C_, 1);

    t3_kernel<<<(BH_ * S_ * 32) / 256, 256>>>(K, u, T3);

    dim3 gsc(S_ / 128, S_ / 128, BH_);                // (16, 16, 32)
    relD_kernel<<<gsc, 256>>>(Q, rr, v, D);
    scores_kernel<<<gsc, 256>>>(Q, K, T3, D, SC);

    softmax_kernel<<<BH_ * S_, 256>>>(SC);

    dim3 gav(1, S_ / 128, BH_);                       // (1, 16, 32)
    av_kernel<<<gav, 256>>>(SC, V, CTX);

    sgemm_nn<<<gproj, 256>>>(CTX, Wo, bo, out, B_ * S_, C_, C_, 0);
}

// round 2
// speedup vs baseline: 1.8453x; 1.8453x over previous
#include <cuda_runtime.h>
#include <math.h>
#include <stdint.h>

#define B_ 2
#define S_ 2048
#define C_ 1024
#define H_ 16
#define D_ 64
#define BH_ (B_*H_)

// ---------------- scratch (static device globals; no allocation) ----------------
__device__ float g_rr[S_*D_];
__device__ float g_Q[(size_t)BH_*S_*D_];
__device__ float g_K[(size_t)BH_*S_*D_];
__device__ float g_V[(size_t)BH_*S_*D_];
__device__ float g_T3[BH_*S_];
__device__ float g_D[(size_t)BH_*S_*S_];
__device__ float g_SC[(size_t)BH_*S_*S_];
__device__ float g_CTX[(size_t)B_*S_*C_];

// ---------------- helpers ----------------
__device__ __forceinline__ uint32_t f2tf(float x) {
    uint32_t r;
    asm("cvt.rna.tf32.f32 %0, %1;" : "=r"(r) : "f"(x));
    return r;
}

__device__ __forceinline__ void mma8(float* c, uint32_t a0, uint32_t a1, uint32_t a2, uint32_t a3,
                                     uint32_t b0, uint32_t b1) {
    asm volatile("mma.sync.aligned.m16n8k8.row.col.f32.tf32.tf32.f32 "
                 "{%0,%1,%2,%3},{%4,%5,%6,%7},{%8,%9},{%0,%1,%2,%3};\n"
                 : "+f"(c[0]), "+f"(c[1]), "+f"(c[2]), "+f"(c[3])
                 : "r"(a0), "r"(a1), "r"(a2), "r"(a3), "r"(b0), "r"(b1));
}

// ---------------- sinusoid relative-position table ----------------
__global__ void rr_kernel(float* __restrict__ rr) {
    int p = blockIdx.x;
    int i = threadIdx.x;
    double invf = exp(-((double)(i & 31)) * (log(10000.0) / 32.0));
    double ang = (double)p * invf;
    rr[p * D_ + i] = (i < 32) ? (float)sin(ang) : (float)cos(ang);
}

// ---------------- tf32 GEMM NN: C[M,N] = A[M,K] @ B[K,N] (+bias, headed remap) ----------------
__global__ __launch_bounds__(256, 2) void gemm_tf32_nn(
    const float* __restrict__ A, const float* __restrict__ Bm,
    const float* __restrict__ bias, float* __restrict__ Co,
    int M, int N, int K, int headed)
{
    __shared__ uint32_t As[16][132];   // [k][m]
    __shared__ uint32_t Bs[16][132];   // [k][n]
    const int tid = threadIdx.x, lane = tid & 31, warp = tid >> 5;
    const int wm = warp >> 2, wn = warp & 3;
    const int m0 = blockIdx.y * 128, n0 = blockIdx.x * 128;
    const int arow = tid >> 2, ac = (tid & 3) * 4;
    const int brow = tid >> 5, bc = (tid & 31) * 4;
    const int tig = lane & 3, grp = lane >> 2;

    float acc[4][4][4];
    #pragma unroll
    for (int i = 0; i < 4; i++)
        #pragma unroll
        for (int j = 0; j < 4; j++)
            #pragma unroll
            for (int e = 0; e < 4; e++) acc[i][j][e] = 0.f;

    float4 ra0 = *(const float4*)(A + (size_t)(m0 + arow) * K + ac);
    float4 ra1 = *(const float4*)(A + (size_t)(m0 + arow + 64) * K + ac);
    float4 rb0 = *(const float4*)(Bm + (size_t)brow * N + n0 + bc);
    float4 rb1 = *(const float4*)(Bm + (size_t)(brow + 8) * N + n0 + bc);

    for (int kt = 0; kt < K; kt += 16) {
        As[ac + 0][arow] = f2tf(ra0.x); As[ac + 1][arow] = f2tf(ra0.y);
        As[ac + 2][arow] = f2tf(ra0.z); As[ac + 3][arow] = f2tf(ra0.w);
        As[ac + 0][arow + 64] = f2tf(ra1.x); As[ac + 1][arow + 64] = f2tf(ra1.y);
        As[ac + 2][arow + 64] = f2tf(ra1.z); As[ac + 3][arow + 64] = f2tf(ra1.w);
        uint4 p0 = {f2tf(rb0.x), f2tf(rb0.y), f2tf(rb0.z), f2tf(rb0.w)};
        uint4 p1 = {f2tf(rb1.x), f2tf(rb1.y), f2tf(rb1.z), f2tf(rb1.w)};
        *(uint4*)&Bs[brow][bc] = p0;
        *(uint4*)&Bs[brow + 8][bc] = p1;
        __syncthreads();
        int kn = kt + 16;
        if (kn < K) {
            ra0 = *(const float4*)(A + (size_t)(m0 + arow) * K + kn + ac);
            ra1 = *(const float4*)(A + (size_t)(m0 + arow + 64) * K + kn + ac);
            rb0 = *(const float4*)(Bm + (size_t)(kn + brow) * N + n0 + bc);
            rb1 = *(const float4*)(Bm + (size_t)(kn + brow + 8) * N + n0 + bc);
        }
        #pragma unroll
        for (int kk = 0; kk < 16; kk += 8) {
            uint32_t af[4][4], bf[4][2];
            #pragma unroll
            for (int mi = 0; mi < 4; mi++) {
                int m = wm * 64 + mi * 16 + grp;
                af[mi][0] = As[kk + tig][m];
                af[mi][1] = As[kk + tig][m + 8];
                af[mi][2] = As[kk + 4 + tig][m];
                af[mi][3] = As[kk + 4 + tig][m + 8];
            }
            #pragma unroll
            for (int ni = 0; ni < 4; ni++) {
                int n = wn * 32 + ni * 8 + grp;
                bf[ni][0] = Bs[kk + tig][n];
                bf[ni][1] = Bs[kk + 4 + tig][n];
            }
            #pragma unroll
            for (int mi = 0; mi < 4; mi++)
                #pragma unroll
                for (int ni = 0; ni < 4; ni++)
                    mma8(acc[mi][ni], af[mi][0], af[mi][1], af[mi][2], af[mi][3],
                         bf[ni][0], bf[ni][1]);
        }
        __syncthreads();
    }

    #pragma unroll
    for (int mi = 0; mi < 4; mi++) {
        #pragma unroll
        for (int ni = 0; ni < 4; ni++) {
            int r0 = m0 + wm * 64 + mi * 16 + grp;
            int c0 = n0 + wn * 32 + ni * 8 + tig * 2;
            #pragma unroll
            for (int e = 0; e < 4; e++) {
                int m = r0 + (e >> 1) * 8;
                int n = c0 + (e & 1);
                float v = acc[mi][ni][e];
                if (bias) v += bias[n];
                if (headed) {
                    int b = m >> 11, s = m & (S_ - 1), h = n >> 6, d = n & 63;
                    Co[(((size_t)(b * H_ + h)) * S_ + s) * D_ + d] = v;
                } else {
                    Co[(size_t)m * N + n] = v;
                }
            }
        }
    }
}

// ---------------- T3[bh][k] = u[h] . K[bh][k] ----------------
__global__ void t3_kernel(const float* __restrict__ Km, const float* __restrict__ u,
                          float* __restrict__ T3)
{
    int warp = (blockIdx.x * blockDim.x + threadIdx.x) >> 5;
    int lane = threadIdx.x & 31;
    if (warp >= BH_ * S_) return;
    int bh = warp >> 11;
    int h = bh & (H_ - 1);
    const float* kr = Km + (size_t)warp * D_;
    float s = kr[lane] * u[h * D_ + lane] + kr[lane + 32] * u[h * D_ + lane + 32];
    #pragma unroll
    for (int o = 16; o; o >>= 1) s += __shfl_xor_sync(0xffffffffu, s, o);
    if (lane == 0) T3[warp] = s;
}

// ---------------- D[bh][q][p] = (Q[bh][q]+v[h]) . rr[p]  — tf32 NT batched, K=64 ----------------
__global__ __launch_bounds__(256, 2) void relD_tf32(
    const float* __restrict__ Q, const float* __restrict__ rr,
    const float* __restrict__ vb, float* __restrict__ D)
{
    const int bh = blockIdx.z, h = bh & (H_ - 1);
    const float* Aq = Q + (size_t)bh * S_ * D_;
    __shared__ uint32_t As[16][132];
    __shared__ uint32_t Bs[16][132];
    const int tid = threadIdx.x, lane = tid & 31, warp = tid >> 5;
    const int wm = warp >> 2, wn = warp & 3;
    const int q0 = blockIdx.y * 128, p0 = blockIdx.x * 128;
    const int arow = tid >> 2, ac = (tid & 3) * 4;
    const int tig = lane & 3, grp = lane >> 2;

    float acc[4][4][4];
    #pragma unroll
    for (int i = 0; i < 4; i++)
        #pragma unroll
        for (int j = 0; j < 4; j++)
            #pragma unroll
            for (int e = 0; e < 4; e++) acc[i][j][e] = 0.f;

    float4 ra0 = *(const float4*)(Aq + (size_t)(q0 + arow) * D_ + ac);
    float4 ra1 = *(const float4*)(Aq + (size_t)(q0 + arow + 64) * D_ + ac);
    float4 rb0 = *(const float4*)(rr + (size_t)(p0 + arow) * D_ + ac);
    float4 rb1 = *(const float4*)(rr + (size_t)(p0 + arow + 64) * D_ + ac);
    float4 vv  = *(const float4*)(vb + h * D_ + ac);

    for (int kt = 0; kt < D_; kt += 16) {
        As[ac + 0][arow] = f2tf(ra0.x + vv.x); As[ac + 1][arow] = f2tf(ra0.y + vv.y);
        As[ac + 2][arow] = f2tf(ra0.z + vv.z); As[ac + 3][arow] = f2tf(ra0.w + vv.w);
        As[ac + 0][arow + 64] = f2tf(ra1.x + vv.x); As[ac + 1][arow + 64] = f2tf(ra1.y + vv.y);
        As[ac + 2][arow + 64] = f2tf(ra1.z + vv.z); As[ac + 3][arow + 64] = f2tf(ra1.w + vv.w);
        Bs[ac + 0][arow] = f2tf(rb0.x); Bs[ac + 1][arow] = f2tf(rb0.y);
        Bs[ac + 2][arow] = f2tf(rb0.z); Bs[ac + 3][arow] = f2tf(rb0.w);
        Bs[ac + 0][arow + 64] = f2tf(rb1.x); Bs[ac + 1][arow + 64] = f2tf(rb1.y);
        Bs[ac + 2][arow + 64] = f2tf(rb1.z); Bs[ac + 3][arow + 64] = f2tf(rb1.w);
        __syncthreads();
        int kn = kt + 16;
        if (kn < D_) {
            ra0 = *(const float4*)(Aq + (size_t)(q0 + arow) * D_ + kn + ac);
            ra1 = *(const float4*)(Aq + (size_t)(q0 + arow + 64) * D_ + kn + ac);
            rb0 = *(const float4*)(rr + (size_t)(p0 + arow) * D_ + kn + ac);
            rb1 = *(const float4*)(rr + (size_t)(p0 + arow + 64) * D_ + kn + ac);
            vv  = *(const float4*)(vb + h * D_ + kn + ac);
        }
        #pragma unroll
        for (int kk = 0; kk < 16; kk += 8) {
            uint32_t af[4][4], bf[4][2];
            #pragma unroll
            for (int mi = 0; mi < 4; mi++) {
                int m = wm * 64 + mi * 16 + grp;
                af[mi][0] = As[kk + tig][m];
                af[mi][1] = As[kk + tig][m + 8];
                af[mi][2] = As[kk + 4 + tig][m];
                af[mi][3] = As[kk + 4 + tig][m + 8];
            }
            #pragma unroll
            for (int ni = 0; ni < 4; ni++) {
                int n = wn * 32 + ni * 8 + grp;
                bf[ni][0] = Bs[kk + tig][n];
                bf[ni][1] = Bs[kk + 4 + tig][n];
            }
            #pragma unroll
            for (int mi = 0; mi < 4; mi++)
                #pragma unroll
                for (int ni = 0; ni < 4; ni++)
                    mma8(acc[mi][ni], af[mi][0], af[mi][1], af[mi][2], af[mi][3],
                         bf[ni][0], bf[ni][1]);
        }
        __syncthreads();
    }

    float* Dp = D + (size_t)bh * S_ * S_;
    #pragma unroll
    for (int mi = 0; mi < 4; mi++)
        #pragma unroll
        for (int ni = 0; ni < 4; ni++) {
            int r0 = q0 + wm * 64 + mi * 16 + grp;
            int c0 = p0 + wn * 32 + ni * 8 + tig * 2;
            #pragma unroll
            for (int e = 0; e < 4; e++)
                Dp[(size_t)(r0 + (e >> 1) * 8) * S_ + c0 + (e & 1)] = acc[mi][ni][e];
        }
}

// ---------------- scores: QK^T + T3 + rel_shift(D), scaled — tf32 NT batched, K=64 ----------------
__global__ __launch_bounds__(256, 2) void scores_tf32(
    const float* __restrict__ Q, const float* __restrict__ Km,
    const float* __restrict__ T3, const float* __restrict__ D,
    float* __restrict__ SC)
{
    const int bh = blockIdx.z;
    const float* Aq = Q + (size_t)bh * S_ * D_;
    const float* Bk = Km + (size_t)bh * S_ * D_;
    __shared__ uint32_t As[16][132];
    __shared__ uint32_t Bs[16][132];
    const int tid = threadIdx.x, lane = tid & 31, warp = tid >> 5;
    const int wm = warp >> 2, wn = warp & 3;
    const int q0 = blockIdx.y * 128, n0 = blockIdx.x * 128;
    const int arow = tid >> 2, ac = (tid & 3) * 4;
    const int tig = lane & 3, grp = lane >> 2;

    float acc[4][4][4];
    #pragma unroll
    for (int i = 0; i < 4; i++)
        #pragma unroll
        for (int j = 0; j < 4; j++)
            #pragma unroll
            for (int e = 0; e < 4; e++) acc[i][j][e] = 0.f;

    float4 ra0 = *(const float4*)(Aq + (size_t)(q0 + arow) * D_ + ac);
    float4 ra1 = *(const float4*)(Aq + (size_t)(q0 + arow + 64) * D_ + ac);
    float4 rb0 = *(const float4*)(Bk + (size_t)(n0 + arow) * D_ + ac);
    float4 rb1 = *(const float4*)(Bk + (size_t)(n0 + arow + 64) * D_ + ac);

    for (int kt = 0; kt < D_; kt += 16) {
        As[ac + 0][arow] = f2tf(ra0.x); As[ac + 1][arow] = f2tf(ra0.y);
        As[ac + 2][arow] = f2tf(ra0.z); As[ac + 3][arow] = f2tf(ra0.w);
        As[ac + 0][arow + 64] = f2tf(ra1.x); As[ac + 1][arow + 64] = f2tf(ra1.y);
        As[ac + 2][arow + 64] = f2tf(ra1.z); As[ac + 3][arow + 64] = f2tf(ra1.w);
        Bs[ac + 0][arow] = f2tf(rb0.x); Bs[ac + 1][arow] = f2tf(rb0.y);
        Bs[ac + 2][arow] = f2tf(rb0.z); Bs[ac + 3][arow] = f2tf(rb0.w);
        Bs[ac + 0][arow + 64] = f2tf(rb1.x); Bs[ac + 1][arow + 64] = f2tf(rb1.y);
        Bs[ac + 2][arow + 64] = f2tf(rb1.z); Bs[ac + 3][arow + 64] = f2tf(rb1.w);
        __syncthreads();
        int kn = kt + 16;
        if (kn < D_) {
            ra0 = *(const float4*)(Aq + (size_t)(q0 + arow) * D_ + kn + ac);
            ra1 = *(const float4*)(Aq + (size_t)(q0 + arow + 64) * D_ + kn + ac);
            rb0 = *(const float4*)(Bk + (size_t)(n0 + arow) * D_ + kn + ac);
            rb1 = *(const float4*)(Bk + (size_t)(n0 + arow + 64) * D_ + kn + ac);
        }
        #pragma unroll
        for (int kk = 0; kk < 16; kk += 8) {
            uint32_t af[4][4], bf[4][2];
            #pragma unroll
            for (int mi = 0; mi < 4; mi++) {
                int m = wm * 64 + mi * 16 + grp;
                af[mi][0] = As[kk + tig][m];
                af[mi][1] = As[kk + tig][m + 8];
                af[mi][2] = As[kk + 4 + tig][m];
                af[mi][3] = As[kk + 4 + tig][m + 8];
            }
            #pragma unroll
            for (int ni = 0; ni < 4; ni++) {
                int n = wn * 32 + ni * 8 + grp;
                bf[ni][0] = Bs[kk + tig][n];
                bf[ni][1] = Bs[kk + 4 + tig][n];
            }
            #pragma unroll
            for (int mi = 0; mi < 4; mi++)
                #pragma unroll
                for (int ni = 0; ni < 4; ni++)
                    mma8(acc[mi][ni], af[mi][0], af[mi][1], af[mi][2], af[mi][3],
                         bf[ni][0], bf[ni][1]);
        }
        __syncthreads();
    }

    const float* Dp = D + (size_t)bh * S_ * S_;
    const float* t3p = T3 + bh * S_;
    float* scp = SC + (size_t)bh * S_ * S_;
    #pragma unroll
    for (int mi = 0; mi < 4; mi++)
        #pragma unroll
        for (int ni = 0; ni < 4; ni++) {
            int r0 = q0 + wm * 64 + mi * 16 + grp;
            int c0 = n0 + wn * 32 + ni * 8 + tig * 2;
            #pragma unroll
            for (int e = 0; e < 4; e++) {
                int q = r0 + (e >> 1) * 8;
                int k = c0 + (e & 1);
                int dq = q - k;
                float sh;
                if (dq >= 0)       sh = Dp[(size_t)q * S_ + dq];
                else if (dq == -1) sh = 0.f;
                else               sh = Dp[(size_t)(q + 1) * S_ + (S_ + 1 + dq)];
                scp[(size_t)q * S_ + k] = (acc[mi][ni][e] + t3p[k] + sh) * 0.125f;
            }
        }
}

// ---------------- row softmax over 2048, in place ----------------
__global__ void softmax_kernel(float* __restrict__ SC)
{
    float* p = SC + (size_t)blockIdx.x * S_;
    const int tid = threadIdx.x;
    float4 v0 = ((float4*)p)[tid];
    float4 v1 = ((float4*)p)[tid + 256];
    float m = fmaxf(fmaxf(fmaxf(v0.x, v0.y), fmaxf(v0.z, v0.w)),
                    fmaxf(fmaxf(v1.x, v1.y), fmaxf(v1.z, v1.w)));
    __shared__ float red[8];
    #pragma unroll
    for (int o = 16; o; o >>= 1) m = fmaxf(m, __shfl_xor_sync(0xffffffffu, m, o));
    if ((tid & 31) == 0) red[tid >> 5] = m;
    __syncthreads();
    m = red[0];
    #pragma unroll
    for (int i = 1; i < 8; i++) m = fmaxf(m, red[i]);
    __syncthreads();

    v0.x = expf(v0.x - m); v0.y = expf(v0.y - m);
    v0.z = expf(v0.z - m); v0.w = expf(v0.w - m);
    v1.x = expf(v1.x - m); v1.y = expf(v1.y - m);
    v1.z = expf(v1.z - m); v1.w = expf(v1.w - m);
    float s = v0.x + v0.y + v0.z + v0.w + v1.x + v1.y + v1.z + v1.w;
    #pragma unroll
    for (int o = 16; o; o >>= 1) s += __shfl_xor_sync(0xffffffffu, s, o);
    if ((tid & 31) == 0) red[tid >> 5] = s;
    __syncthreads();
    s = red[0];
    #pragma unroll
    for (int i = 1; i < 8; i++) s += red[i];
    float inv = 1.f / s;
    v0.x *= inv; v0.y *= inv; v0.z *= inv; v0.w *= inv;
    v1.x *= inv; v1.y *= inv; v1.z *= inv; v1.w *= inv;
    ((float4*)p)[tid] = v0;
    ((float4*)p)[tid + 256] = v1;
}

// ---------------- ctx = attn @ V — tf32 NN batched, BM=128 BN=64 BK=32 ----------------
__global__ __launch_bounds__(256, 2) void av_tf32(
    const float* __restrict__ SC, const float* __restrict__ V,
    float* __restrict__ CTX)
{
    const int bh = blockIdx.z, b = bh >> 4, h = bh & 15;
    const float* A = SC + (size_t)bh * S_ * S_;
    const float* Bv = V + (size_t)bh * S_ * D_;
    __shared__ uint32_t As[32][132];   // [k][m]
    __shared__ uint32_t Bs[32][68];    // [k][n]
    const int tid = threadIdx.x, lane = tid & 31, warp = tid >> 5;
    const int wm = warp >> 2, wn = warp & 3;
    const int q0 = blockIdx.y * 128;
    const int arow = tid >> 3, ac = (tid & 7) * 4;
    const int brow = tid >> 4, bc = (tid & 15) * 4;
    const int tig = lane & 3, grp = lane >> 2;

    float acc[4][2][4];
    #pragma unroll
    for (int i = 0; i < 4; i++)
        #pragma unroll
        for (int j = 0; j < 2; j++)
            #pragma unroll
            for (int e = 0; e < 4; e++) acc[i][j][e] = 0.f;

    float4 ra[4], rb[2];
    #pragma unroll
    for (int i = 0; i < 4; i++)
        ra[i] = *(const float4*)(A + (size_t)(q0 + arow + 32 * i) * S_ + ac);
    #pragma unroll
    for (int i = 0; i < 2; i++)
        rb[i] = *(const float4*)(Bv + (size_t)(brow + 16 * i) * D_ + bc);

    for (int kt = 0; kt < S_; kt += 32) {
        #pragma unroll
        for (int i = 0; i < 4; i++) {
            As[ac + 0][arow + 32 * i] = f2tf(ra[i].x);
            As[ac + 1][arow + 32 * i] = f2tf(ra[i].y);
            As[ac + 2][arow + 32 * i] = f2tf(ra[i].z);
            As[ac + 3][arow + 32 * i] = f2tf(ra[i].w);
        }
        #pragma unroll
        for (int i = 0; i < 2; i++) {
            uint4 pb = {f2tf(rb[i].x), f2tf(rb[i].y), f2tf(rb[i].z), f2tf(rb[i].w)};
            *(uint4*)&Bs[brow + 16 * i][bc] = pb;
        }
        __syncthreads();
        int kn = kt + 32;
        if (kn < S_) {
            #pragma unroll
            for (int i = 0; i < 4; i++)
                ra[i] = *(const float4*)(A + (size_t)(q0 + arow + 32 * i) * S_ + kn + ac);
            #pragma unroll
            for (int i = 0; i < 2; i++)
                rb[i] = *(const float4*)(Bv + (size_t)(kn + brow + 16 * i) * D_ + bc);
        }
        #pragma unroll
        for (int kk = 0; kk < 32; kk += 8) {
            uint32_t af[4][4], bf[2][2];
            #pragma unroll
            for (int mi = 0; mi < 4; mi++) {
                int m = wm * 64 + mi * 16 + grp;
                af[mi][0] = As[kk + tig][m];
                af[mi][1] = As[kk + tig][m + 8];
                af[mi][2] = As[kk + 4 + tig][m];
                af[mi][3] = As[kk + 4 + tig][m + 8];
            }
            #pragma unroll
            for (int ni = 0; ni < 2; ni++) {
                int n = wn * 16 + ni * 8 + grp;
                bf[ni][0] = Bs[kk + tig][n];
                bf[ni][1] = Bs[kk + 4 + tig][n];
            }
            #pragma unroll
            for (int mi = 0; mi < 4; mi++)
                #pragma unroll
                for (int ni = 0; ni < 2; ni++)
                    mma8(acc[mi][ni], af[mi][0], af[mi][1], af[mi][2], af[mi][3],
                         bf[ni][0], bf[ni][1]);
        }
        __syncthreads();
    }

    #pragma unroll
    for (int mi = 0; mi < 4; mi++)
        #pragma unroll
        for (int ni = 0; ni < 2; ni++) {
            int r0 = q0 + wm * 64 + mi * 16 + grp;
            int c0 = wn * 16 + ni * 8 + tig * 2;
            #pragma unroll
            for (int e = 0; e < 4; e++) {
                int q = r0 + (e >> 1) * 8;
                int d = c0 + (e & 1);
                CTX[((size_t)b * S_ + q) * C_ + h * D_ + d] = acc[mi][ni][e];
            }
        }
}

// ---------------- launch ----------------
extern "C" void kernel_launch(void* const* d_in, const int* in_sizes, int n_in,
                              void* d_out, int out_size)
{
    const float* x  = (const float*)d_in[0];
    const float* Wq = (const float*)d_in[1];
    const float* Wk = (const float*)d_in[2];
    const float* Wv = (const float*)d_in[3];
    const float* u  = (const float*)d_in[4];
    const float* v  = (const float*)d_in[5];
    const float* Wo = (const float*)d_in[6];
    const float* bo = (const float*)d_in[7];
    float* out = (float*)d_out;

    float *rr, *Q, *K, *V, *T3, *D, *SC, *CTX;
    cudaGetSymbolAddress((void**)&rr,  g_rr);
    cudaGetSymbolAddress((void**)&Q,   g_Q);
    cudaGetSymbolAddress((void**)&K,   g_K);
    cudaGetSymbolAddress((void**)&V,   g_V);
    cudaGetSymbolAddress((void**)&T3,  g_T3);
    cudaGetSymbolAddress((void**)&D,   g_D);
    cudaGetSymbolAddress((void**)&SC,  g_SC);
    cudaGetSymbolAddress((void**)&CTX, g_CTX);

    rr_kernel<<<S_, 64>>>(rr);

    dim3 gproj(C_ / 128, (B_ * S_) / 128);
    gemm_tf32_nn<<<gproj, 256>>>(x, Wq, nullptr, Q, B_ * S_, C_, C_, 1);
    gemm_tf32_nn<<<gproj, 256>>>(x, Wk, nullptr, K, B_ * S_, C_, C_, 1);
    gemm_tf32_nn<<<gproj, 256>>>(x, Wv, nullptr, V, B_ * S_, C_, C_, 1);

    t3_kernel<<<(BH_ * S_ * 32) / 256, 256>>>(K, u, T3);

    dim3 gsc(S_ / 128, S_ / 128, BH_);
    relD_tf32<<<gsc, 256>>>(Q, rr, v, D);
    scores_tf32<<<gsc, 256>>>(Q, K, T3, D, SC);

    softmax_kernel<<<BH_ * S_, 256>>>(SC);

    dim3 gav(1, S_ / 128, BH_);
    av_tf32<<<gav, 256>>>(SC, V, CTX);

    gemm_tf32_nn<<<gproj, 256>>>(CTX, Wo, bo, out, B_ * S_, C_, C_, 0);
}